// round 13
// baseline (speedup 1.0000x reference)
#include <cuda_runtime.h>
#include <cuda_fp16.h>
#include <cstdint>
#include <math.h>

#define BTOK 4096
#define DIM 1024
#define HID 4096
#define NE 8
#define NSLOT (BTOK*2)
#define CAP 9216
#define MTILES (CAP/128)      // 72

// ---------------- scratch (device globals; no runtime allocation) ----------------
__device__ __align__(128) float  g_xn[BTOK*DIM];                 // pooled (fp32)
__device__ __align__(128) __half g_xf[BTOK*DIM];                 // x_norm fp16
__device__ __align__(128) __half g_hf[(size_t)CAP*HID];          // hidden fp16
__device__ __align__(128) float  g_y[(size_t)CAP*DIM];           // expert outputs
__device__ __align__(128) __half g_w1f[(size_t)NE*HID*DIM];
__device__ __align__(128) __half g_w2f[(size_t)NE*DIM*HID];
__device__ int   g_tok[CAP];
__device__ int   g_slot[NSLOT];
__device__ float g_topw[NSLOT];
__device__ int   g_topi[NSLOT];
__device__ int   g_cnt[NE];
__device__ int   g_off[NE+1];
__device__ int   g_tile_e[MTILES];

// ---------------- helpers ----------------
__device__ __forceinline__ void cp16(uint32_t dst, const void* src){
    asm volatile("cp.async.cg.shared.global [%0], [%1], 16;\n" :: "r"(dst), "l"(src));
}
__device__ __forceinline__ void mma_f16(float* c, const uint32_t* a, const uint32_t* b){
    asm volatile("mma.sync.aligned.m16n8k16.row.col.f32.f16.f16.f32 "
        "{%0,%1,%2,%3}, {%4,%5,%6,%7}, {%8,%9}, {%0,%1,%2,%3};"
        : "+f"(c[0]), "+f"(c[1]), "+f"(c[2]), "+f"(c[3])
        : "r"(a[0]), "r"(a[1]), "r"(a[2]), "r"(a[3]), "r"(b[0]), "r"(b[1]));
}
// word index in a [rows x 32-word] smem tile; 16B-unit swizzle u ^= (r&7)
__device__ __forceinline__ int swz32(int r, int w){
    return r*32 + (((((w>>2)) ^ (r & 7)) << 2) | (w & 3));
}
__device__ __forceinline__ uint2 h4(float4 v){
    __half2 lo = __floats2half2_rn(v.x, v.y);
    __half2 hi = __floats2half2_rn(v.z, v.w);
    uint2 r; r.x = *(uint32_t*)&lo; r.y = *(uint32_t*)&hi; return r;
}

// ---------------- fused init + weight-convert + pool ----------------
__global__ void pool_k(const float* __restrict__ x,
                       const float* __restrict__ w1, const float* __restrict__ w2){
    const int t = threadIdx.x;
    if (t < 32){
        size_t i = (size_t)blockIdx.x*16 + (t & 15);
        const float4* src = (t < 16) ? (const float4*)w1 : (const float4*)w2;
        __half* dst = (t < 16) ? g_w1f : g_w2f;
        *(uint2*)(dst + i*4) = h4(src[i]);
    }
    if (blockIdx.x == 0){
        if (t < NE) g_cnt[t] = 0;
        if (t < MTILES) g_tile_e[t] = -1;
        for (int i = t; i < CAP; i += 256) g_tok[i] = 0;
    }
    int g = blockIdx.x*blockDim.x + t;
    int row = g >> 5, lane = g & 31;
    float2 v = ((const float2*)(x + (size_t)row*64))[lane];
    float s = v.x + v.y;
#pragma unroll
    for (int o=16;o;o>>=1) s += __shfl_xor_sync(0xffffffffu, s, o);
    if (!lane) g_xn[row] = s * (1.0f/64.0f);
}

__global__ void __launch_bounds__(256) lngate_k(const float* __restrict__ gamma,
                                                const float* __restrict__ beta,
                                                const float* __restrict__ wg,
                                                const float* __restrict__ bg){
    const int b = blockIdx.x, t = threadIdx.x;
    __shared__ float srow[DIM];
    __shared__ float rs[8], rss[8], slog[8];
    float4 v = ((const float4*)(g_xn + (size_t)b*DIM))[t];
    float s  = (v.x+v.y)+(v.z+v.w);
    float ss = (v.x*v.x+v.y*v.y)+(v.z*v.z+v.w*v.w);
#pragma unroll
    for (int o=16;o;o>>=1){ s += __shfl_xor_sync(0xffffffffu, s, o); ss += __shfl_xor_sync(0xffffffffu, ss, o); }
    const int lane = t & 31, w = t >> 5;
    if (!lane){ rs[w]=s; rss[w]=ss; }
    __syncthreads();
    float tot=0.f, tot2=0.f;
#pragma unroll
    for (int i=0;i<8;i++){ tot += rs[i]; tot2 += rss[i]; }
    const float mean = tot * (1.0f/DIM);
    const float var  = tot2 * (1.0f/DIM) - mean*mean;
    const float rinv = rsqrtf(var + 1e-5f);
    float4 g4 = ((const float4*)gamma)[t];
    float4 be4 = ((const float4*)beta)[t];
    float4 xn;
    xn.x = (v.x-mean)*rinv*g4.x + be4.x;
    xn.y = (v.y-mean)*rinv*g4.y + be4.y;
    xn.z = (v.z-mean)*rinv*g4.z + be4.z;
    xn.w = (v.w-mean)*rinv*g4.w + be4.w;
    ((float4*)srow)[t] = xn;                 // full precision for gating
    *(uint2*)(g_xf + (size_t)b*DIM + 4*t) = h4(xn);
    __syncthreads();
    const float4* wrow = (const float4*)(wg + (size_t)w*DIM);
    const float4* sr = (const float4*)srow;
    float acc = 0.f;
#pragma unroll
    for (int i=0;i<8;i++){
        int idx = lane + i*32;
        float4 a = sr[idx], ww = wrow[idx];
        acc += a.x*ww.x + a.y*ww.y + a.z*ww.z + a.w*ww.w;
    }
#pragma unroll
    for (int o=16;o;o>>=1) acc += __shfl_xor_sync(0xffffffffu, acc, o);
    if (!lane) slog[w] = acc + bg[w];
    __syncthreads();
    if (!t){
        int e0 = 0;
#pragma unroll
        for (int i=1;i<8;i++) if (slog[i] > slog[e0]) e0 = i;
        int e1 = (e0==0) ? 1 : 0;
#pragma unroll
        for (int i=0;i<8;i++) if (i!=e0 && slog[i] > slog[e1]) e1 = i;
        float z = expf(slog[e1] - slog[e0]);      // v1 <= v0
        g_topi[b*2]=e0; g_topi[b*2+1]=e1;
        g_topw[b*2]=1.0f/(1.0f+z); g_topw[b*2+1]=z/(1.0f+z);
        atomicAdd(&g_cnt[e0],1); atomicAdd(&g_cnt[e1],1);
    }
}

// fused scan + scatter: single block, smem counters
__global__ void __launch_bounds__(256) scanscatter_k(){
    __shared__ int cur[NE];
    const int t = threadIdx.x;
    if (t == 0){
        int off = 0;
        for (int e=0;e<NE;e++){
            g_off[e] = off;
            int nt = (g_cnt[e] + 127) >> 7;
            int t0 = off >> 7;
            for (int i=0;i<nt;i++) g_tile_e[t0+i] = e;
            off += nt << 7;
        }
        g_off[NE] = off;
    }
    if (t < NE) cur[t] = 0;
    __syncthreads();
    for (int i=t; i<NSLOT; i+=256){
        int e = g_topi[i];
        int p = g_off[e] + atomicAdd(&cur[e], 1);
        g_tok[p] = i >> 1;
        g_slot[i] = p;
    }
}

// ---------------- fp16 mma GEMM: CTA tile 128x128, warp tile 64x32, K-chunk 64 ----------------
// 3-stage ring: stage = A[128x32w] (16KB) + B[128x32w] (16KB) = 32KB; 96KB total
// -> 2 CTAs/SM (4 warps/SMSP) for latency coverage. acc = 64 regs/thread.
template<int KD, int ND, bool GATHER, bool SILU>
__global__ void __launch_bounds__(256,2) gemm_k(const __half* __restrict__ W,
                                                const float* __restrict__ bias){
    extern __shared__ __align__(16) char smem[];
    uint32_t* SW = (uint32_t*)smem;
    const int ntile = blockIdx.x, mtile = blockIdx.y;
    const int e = g_tile_e[mtile];
    if (e < 0) return;
    const int t = threadIdx.x;

    const int r0 = t >> 3, u = t & 7;                        // r0: 0..31, u: 16B unit
    const int adst0 = r0*32 + ((u ^ (r0 & 7)) << 2);         // words; +i*1024 per +32 rows

    const __half* aptr[4];
    if (GATHER){
#pragma unroll
        for (int i=0;i<4;i++)
            aptr[i] = g_xf + (size_t)g_tok[mtile*128 + r0 + i*32]*KD + u*8;
    } else {
        aptr[0] = g_hf + (size_t)(mtile*128 + r0)*KD + u*8;
    }
    const __half* bbase = W + ((size_t)e*ND + ntile*128 + r0)*KD + u*8;
    const float* bias_e = bias + (size_t)e*ND;
    uint32_t sAu = (uint32_t)__cvta_generic_to_shared(SW);

    const int NK = KD/64;
    // prologue: stages 0,1  (stage stride 8192 words = 32KB)
#pragma unroll
    for (int c=0;c<2;c++){
        const int ko = c*64;
        const uint32_t sb = sAu + (uint32_t)(c*8192 + adst0)*4u;
#pragma unroll
        for (int i=0;i<4;i++)
            cp16(sb + i*4096u, (GATHER ? aptr[i] : aptr[0] + (size_t)i*32*KD) + ko);
#pragma unroll
        for (int i=0;i<4;i++)
            cp16(sb + 16384u + i*4096u, bbase + (size_t)i*32*KD + ko);
        asm volatile("cp.async.commit_group;\n");
    }

    const int w = t>>5, lane = t&31;
    const int wm = w & 1, wn = w >> 1;        // 2 x 4 warp grid; warp tile 64x32
    const int lr = lane >> 2, lc = lane & 3;
    float acc[4][4][4];
#pragma unroll
    for (int a=0;a<4;a++)
#pragma unroll
        for (int bb=0;bb<4;bb++)
#pragma unroll
            for (int c=0;c<4;c++) acc[a][bb][c] = 0.f;

    int buf = 0;
    for (int kc=0; kc<NK; kc++){
        asm volatile("cp.async.wait_group 1;\n");
        __syncthreads();
        if (kc+2 < NK){
            const int ko = (kc+2)*64;
            int nb = buf + 2; if (nb >= 3) nb -= 3;
            const uint32_t sb = sAu + (uint32_t)(nb*8192 + adst0)*4u;
#pragma unroll
            for (int i=0;i<4;i++)
                cp16(sb + i*4096u, (GATHER ? aptr[i] : aptr[0] + (size_t)i*32*KD) + ko);
#pragma unroll
            for (int i=0;i<4;i++)
                cp16(sb + 16384u + i*4096u, bbase + (size_t)i*32*KD + ko);
        }
        asm volatile("cp.async.commit_group;\n");

        const uint32_t* SA = SW + buf*8192;
        const uint32_t* SB = SA + 4096;
#pragma unroll
        for (int s=0;s<4;s++){
            const int w0 = s*8 + lc;
            uint32_t bfr[4][2];
#pragma unroll
            for (int ni=0;ni<4;ni++){
                const int n = wn*32 + ni*8 + lr;
                bfr[ni][0] = SB[swz32(n, w0)];
                bfr[ni][1] = SB[swz32(n, w0+4)];
            }
#pragma unroll
            for (int mi=0;mi<4;mi++){
                const int r = wm*64 + mi*16 + lr;
                uint32_t afr[4];
                afr[0] = SA[swz32(r,   w0)];
                afr[1] = SA[swz32(r+8, w0)];
                afr[2] = SA[swz32(r,   w0+4)];
                afr[3] = SA[swz32(r+8, w0+4)];
#pragma unroll
                for (int ni=0;ni<4;ni++)
                    mma_f16(acc[mi][ni], afr, bfr[ni]);
            }
        }
        buf++; if (buf >= 3) buf = 0;
    }

#pragma unroll
    for (int mi=0;mi<4;mi++){
        const int rb = mtile*128 + wm*64 + mi*16 + lr;
#pragma unroll
        for (int ni=0;ni<4;ni++){
            const int nb = ntile*128 + wn*32 + ni*8 + lc*2;
            const float b0 = bias_e[nb], b1v = bias_e[nb+1];
#pragma unroll
            for (int h=0; h<2; h++){
                const int p = rb + h*8;
                float v0 = acc[mi][ni][h*2+0] + b0;
                float v1 = acc[mi][ni][h*2+1] + b1v;
                if (SILU){
                    v0 = v0 / (1.0f + expf(-v0));
                    v1 = v1 / (1.0f + expf(-v1));
                    __half2 hv = __floats2half2_rn(v0, v1);
                    *(uint32_t*)(g_hf + (size_t)p*ND + nb) = *(uint32_t*)&hv;
                } else {
                    *(float2*)(g_y + (size_t)p*ND + nb) = make_float2(v0, v1);
                }
            }
        }
    }
}

// ---------------- coalesced residual ----------------
__global__ void __launch_bounds__(256) resid_k(const float* __restrict__ x,
                                               float* __restrict__ out){
    __shared__ float sf[256];
    const int t = threadIdx.x;
    const int base = blockIdx.x * 256;            // first (b,d) row
    const int b = base >> 10;
    const int d = (base & 1023) + t;
    const int p0 = g_slot[2*b], p1 = g_slot[2*b+1];
    sf[t] = g_topw[2*b]   * g_y[(size_t)p0*DIM + d]
          + g_topw[2*b+1] * g_y[(size_t)p1*DIM + d];
    __syncthreads();
    const float4* xi = (const float4*)(x + (size_t)base*64);
    float4* o = (float4*)(out + (size_t)base*64);
#pragma unroll 4
    for (int i=t; i<4096; i+=256){                // 256 rows x 16 float4
        float f = sf[i >> 4];
        float4 v = xi[i];
        v.x += f; v.y += f; v.z += f; v.w += f;
        o[i] = v;
    }
}

// ---------------- launch ----------------
extern "C" void kernel_launch(void* const* d_in, const int* in_sizes, int n_in,
                              void* d_out, int out_size){
    const float* x     = (const float*)d_in[0];
    const float* gamma = (const float*)d_in[1];
    const float* beta  = (const float*)d_in[2];
    const float* wg    = (const float*)d_in[3];
    const float* bg    = (const float*)d_in[4];
    const float* w1    = (const float*)d_in[5];
    const float* b1    = (const float*)d_in[6];
    const float* w2    = (const float*)d_in[7];
    const float* b2    = (const float*)d_in[8];
    float* out = (float*)d_out;

    __half *w1f, *w2f;
    cudaGetSymbolAddress((void**)&w1f, g_w1f);
    cudaGetSymbolAddress((void**)&w2f, g_w2f);

    cudaFuncSetAttribute(gemm_k<DIM, HID, true,  true >, cudaFuncAttributeMaxDynamicSharedMemorySize, 98304);
    cudaFuncSetAttribute(gemm_k<HID, DIM, false, false>, cudaFuncAttributeMaxDynamicSharedMemorySize, 98304);

    pool_k<<<(BTOK*DIM*32)/256, 256>>>(x, w1, w2);    // 1: init + weight-convert + pool
    lngate_k<<<BTOK, 256>>>(gamma, beta, wg, bg);      // 2
    scanscatter_k<<<1, 256>>>();                       // 3
    gemm_k<DIM, HID, true,  true ><<<dim3(HID/128, MTILES), 256, 98304>>>(w1f, b1);   // 4 <- ncu
    gemm_k<HID, DIM, false, false><<<dim3(DIM/128, MTILES), 256, 98304>>>(w2f, b2);   // 5
    resid_k<<<(BTOK*DIM)/256, 256>>>(x, out);          // 6
}

// round 14
// speedup vs baseline: 1.1420x; 1.1420x over previous
#include <cuda_runtime.h>
#include <cuda_fp16.h>
#include <cstdint>
#include <math.h>

#define BTOK 4096
#define DIM 1024
#define HID 4096
#define NE 8
#define NSLOT (BTOK*2)
#define CAP 9216
#define MTILES (CAP/128)      // 72

// ---------------- scratch (device globals; no runtime allocation) ----------------
__device__ __align__(128) float  g_xn[BTOK*DIM];                 // pooled (fp32)
__device__ __align__(128) __half g_xf[BTOK*DIM];                 // x_norm fp16
__device__ __align__(128) __half g_hf[(size_t)CAP*HID];          // hidden fp16
__device__ __align__(128) float  g_y[(size_t)CAP*DIM];           // expert outputs
__device__ __align__(128) __half g_w1f[(size_t)NE*HID*DIM];
__device__ __align__(128) __half g_w2f[(size_t)NE*DIM*HID];
__device__ int   g_tok[CAP];
__device__ int   g_slot[NSLOT];
__device__ float g_topw[NSLOT];
__device__ int   g_topi[NSLOT];
__device__ int   g_cnt[NE];
__device__ int   g_off[NE+1];
__device__ int   g_tile_e[MTILES];
__device__ int   g_done;

// ---------------- helpers ----------------
__device__ __forceinline__ void cp16(uint32_t dst, const void* src){
    asm volatile("cp.async.cg.shared.global [%0], [%1], 16;\n" :: "r"(dst), "l"(src));
}
__device__ __forceinline__ void mma_f16(float* c, const uint32_t* a, const uint32_t* b){
    asm volatile("mma.sync.aligned.m16n8k16.row.col.f32.f16.f16.f32 "
        "{%0,%1,%2,%3}, {%4,%5,%6,%7}, {%8,%9}, {%0,%1,%2,%3};"
        : "+f"(c[0]), "+f"(c[1]), "+f"(c[2]), "+f"(c[3])
        : "r"(a[0]), "r"(a[1]), "r"(a[2]), "r"(a[3]), "r"(b[0]), "r"(b[1]));
}
// word index in a [rows x 32-word] smem tile; 16B-unit swizzle u ^= (r&7)
__device__ __forceinline__ int swz32(int r, int w){
    return r*32 + (((((w>>2)) ^ (r & 7)) << 2) | (w & 3));
}
__device__ __forceinline__ uint2 h4(float4 v){
    __half2 lo = __floats2half2_rn(v.x, v.y);
    __half2 hi = __floats2half2_rn(v.z, v.w);
    uint2 r; r.x = *(uint32_t*)&lo; r.y = *(uint32_t*)&hi; return r;
}

// ---------------- fused init + weight-convert + pool ----------------
__global__ void pool_k(const float* __restrict__ x,
                       const float* __restrict__ w1, const float* __restrict__ w2){
    const int t = threadIdx.x;
    if (t < 32){
        size_t i = (size_t)blockIdx.x*16 + (t & 15);
        const float4* src = (t < 16) ? (const float4*)w1 : (const float4*)w2;
        __half* dst = (t < 16) ? g_w1f : g_w2f;
        *(uint2*)(dst + i*4) = h4(src[i]);
    }
    if (blockIdx.x == 0){
        if (t == 0) g_done = 0;
        if (t < NE) g_cnt[t] = 0;
        if (t < MTILES) g_tile_e[t] = -1;
        for (int i = t; i < CAP; i += 256) g_tok[i] = 0;
    }
    int g = blockIdx.x*blockDim.x + t;
    int row = g >> 5, lane = g & 31;
    float2 v = ((const float2*)(x + (size_t)row*64))[lane];
    float s = v.x + v.y;
#pragma unroll
    for (int o=16;o;o>>=1) s += __shfl_xor_sync(0xffffffffu, s, o);
    if (!lane) g_xn[row] = s * (1.0f/64.0f);
}

// ---------------- layernorm + gate + (last block) scan/scatter ----------------
__global__ void __launch_bounds__(256) lngate_k(const float* __restrict__ gamma,
                                                const float* __restrict__ beta,
                                                const float* __restrict__ wg,
                                                const float* __restrict__ bg){
    const int b = blockIdx.x, t = threadIdx.x;
    __shared__ float srow[DIM];
    __shared__ float rs[8], rss[8], slog[8];
    __shared__ int slast;
    float4 v = ((const float4*)(g_xn + (size_t)b*DIM))[t];
    float s  = (v.x+v.y)+(v.z+v.w);
    float ss = (v.x*v.x+v.y*v.y)+(v.z*v.z+v.w*v.w);
#pragma unroll
    for (int o=16;o;o>>=1){ s += __shfl_xor_sync(0xffffffffu, s, o); ss += __shfl_xor_sync(0xffffffffu, ss, o); }
    const int lane = t & 31, w = t >> 5;
    if (!lane){ rs[w]=s; rss[w]=ss; }
    __syncthreads();
    float tot=0.f, tot2=0.f;
#pragma unroll
    for (int i=0;i<8;i++){ tot += rs[i]; tot2 += rss[i]; }
    const float mean = tot * (1.0f/DIM);
    const float var  = tot2 * (1.0f/DIM) - mean*mean;
    const float rinv = rsqrtf(var + 1e-5f);
    float4 g4 = ((const float4*)gamma)[t];
    float4 be4 = ((const float4*)beta)[t];
    float4 xn;
    xn.x = (v.x-mean)*rinv*g4.x + be4.x;
    xn.y = (v.y-mean)*rinv*g4.y + be4.y;
    xn.z = (v.z-mean)*rinv*g4.z + be4.z;
    xn.w = (v.w-mean)*rinv*g4.w + be4.w;
    ((float4*)srow)[t] = xn;                 // full precision for gating
    *(uint2*)(g_xf + (size_t)b*DIM + 4*t) = h4(xn);
    __syncthreads();
    const float4* wrow = (const float4*)(wg + (size_t)w*DIM);
    const float4* sr = (const float4*)srow;
    float acc = 0.f;
#pragma unroll
    for (int i=0;i<8;i++){
        int idx = lane + i*32;
        float4 a = sr[idx], ww = wrow[idx];
        acc += a.x*ww.x + a.y*ww.y + a.z*ww.z + a.w*ww.w;
    }
#pragma unroll
    for (int o=16;o;o>>=1) acc += __shfl_xor_sync(0xffffffffu, acc, o);
    if (!lane) slog[w] = acc + bg[w];
    __syncthreads();
    if (!t){
        int e0 = 0;
#pragma unroll
        for (int i=1;i<8;i++) if (slog[i] > slog[e0]) e0 = i;
        int e1 = (e0==0) ? 1 : 0;
#pragma unroll
        for (int i=0;i<8;i++) if (i!=e0 && slog[i] > slog[e1]) e1 = i;
        float z = expf(slog[e1] - slog[e0]);      // v1 <= v0
        g_topi[b*2]=e0; g_topi[b*2+1]=e1;
        g_topw[b*2]=1.0f/(1.0f+z); g_topw[b*2+1]=z/(1.0f+z);
        atomicAdd(&g_cnt[e0],1); atomicAdd(&g_cnt[e1],1);
        __threadfence();
        int ticket = atomicAdd(&g_done, 1);
        slast = (ticket == BTOK-1) ? 1 : 0;
    }
    __syncthreads();
    // last-arriving block performs scan + scatter for the whole grid
    if (slast){
        __shared__ int cur[NE];
        if (t == 0){
            int off = 0;
            for (int e=0;e<NE;e++){
                g_off[e] = off;
                int nt = (g_cnt[e] + 127) >> 7;
                int t0 = off >> 7;
                for (int i=0;i<nt;i++) g_tile_e[t0+i] = e;
                off += nt << 7;
            }
            g_off[NE] = off;
        }
        if (t < NE) cur[t] = 0;
        __syncthreads();
        for (int i=t; i<NSLOT; i+=256){
            int e = g_topi[i];
            int p = g_off[e] + atomicAdd(&cur[e], 1);
            g_tok[p] = i >> 1;
            g_slot[i] = p;
        }
    }
}

// ---------------- fp16 mma GEMM: CTA tile 128x256, warp tile 64x64, K-chunk 64 ----------------
// (R10 config: at the legacy-HMMA f32-acc roofline.) 4-stage ring, 192KB, 1 CTA/SM.
template<int KD, int ND, bool GATHER, bool SILU>
__global__ void __launch_bounds__(256) gemm_k(const __half* __restrict__ W,
                                              const float* __restrict__ bias){
    extern __shared__ __align__(16) char smem[];
    uint32_t* SW = (uint32_t*)smem;
    const int ntile = blockIdx.x, mtile = blockIdx.y;
    const int e = g_tile_e[mtile];
    if (e < 0) return;
    const int t = threadIdx.x;

    const int r0 = t >> 3, u = t & 7;                        // r0: 0..31, u: 16B unit
    const int adst0 = r0*32 + ((u ^ (r0 & 7)) << 2);         // words; +i*1024 per +32 rows

    const __half* aptr[4];
    if (GATHER){
#pragma unroll
        for (int i=0;i<4;i++)
            aptr[i] = g_xf + (size_t)g_tok[mtile*128 + r0 + i*32]*KD + u*8;
    } else {
        aptr[0] = g_hf + (size_t)(mtile*128 + r0)*KD + u*8;
    }
    const __half* bbase = W + ((size_t)e*ND + ntile*256 + r0)*KD + u*8;
    const float* bias_e = bias + (size_t)e*ND;
    uint32_t sAu = (uint32_t)__cvta_generic_to_shared(SW);

    const int NK = KD/64;
#pragma unroll
    for (int c=0;c<3;c++){
        const int ko = c*64;
        const uint32_t sb = sAu + (uint32_t)(c*12288 + adst0)*4u;
#pragma unroll
        for (int i=0;i<4;i++)
            cp16(sb + i*4096u, (GATHER ? aptr[i] : aptr[0] + (size_t)i*32*KD) + ko);
#pragma unroll
        for (int i=0;i<8;i++)
            cp16(sb + 16384u + i*4096u, bbase + (size_t)i*32*KD + ko);
        asm volatile("cp.async.commit_group;\n");
    }

    const int w = t>>5, lane = t&31;
    const int wm = w & 1, wn = w >> 1;        // 2 x 4 warp grid; warp tile 64x64
    const int lr = lane >> 2, lc = lane & 3;
    float acc[4][8][4];
#pragma unroll
    for (int a=0;a<4;a++)
#pragma unroll
        for (int bb=0;bb<8;bb++)
#pragma unroll
            for (int c=0;c<4;c++) acc[a][bb][c] = 0.f;

    for (int kc=0; kc<NK; kc++){
        const int buf = kc & 3;
        asm volatile("cp.async.wait_group 2;\n");
        __syncthreads();
        if (kc+3 < NK){
            const int ko = (kc+3)*64;
            const uint32_t sb = sAu + (uint32_t)(((kc+3)&3)*12288 + adst0)*4u;
#pragma unroll
            for (int i=0;i<4;i++)
                cp16(sb + i*4096u, (GATHER ? aptr[i] : aptr[0] + (size_t)i*32*KD) + ko);
#pragma unroll
            for (int i=0;i<8;i++)
                cp16(sb + 16384u + i*4096u, bbase + (size_t)i*32*KD + ko);
        }
        asm volatile("cp.async.commit_group;\n");

        const uint32_t* SA = SW + buf*12288;
        const uint32_t* SB = SA + 4096;
#pragma unroll
        for (int s=0;s<4;s++){
            const int w0 = s*8 + lc;
            uint32_t bfr[8][2];
#pragma unroll
            for (int ni=0;ni<8;ni++){
                const int n = wn*64 + ni*8 + lr;
                bfr[ni][0] = SB[swz32(n, w0)];
                bfr[ni][1] = SB[swz32(n, w0+4)];
            }
#pragma unroll
            for (int mi=0;mi<4;mi++){
                const int r = wm*64 + mi*16 + lr;
                uint32_t afr[4];
                afr[0] = SA[swz32(r,   w0)];
                afr[1] = SA[swz32(r+8, w0)];
                afr[2] = SA[swz32(r,   w0+4)];
                afr[3] = SA[swz32(r+8, w0+4)];
#pragma unroll
                for (int ni=0;ni<8;ni++)
                    mma_f16(acc[mi][ni], afr, bfr[ni]);
            }
        }
    }

#pragma unroll
    for (int mi=0;mi<4;mi++){
        const int rb = mtile*128 + wm*64 + mi*16 + lr;
#pragma unroll
        for (int ni=0;ni<8;ni++){
            const int nb = ntile*256 + wn*64 + ni*8 + lc*2;
            const float b0 = bias_e[nb], b1v = bias_e[nb+1];
#pragma unroll
            for (int h=0; h<2; h++){
                const int p = rb + h*8;
                float v0 = acc[mi][ni][h*2+0] + b0;
                float v1 = acc[mi][ni][h*2+1] + b1v;
                if (SILU){
                    v0 = v0 / (1.0f + expf(-v0));
                    v1 = v1 / (1.0f + expf(-v1));
                    __half2 hv = __floats2half2_rn(v0, v1);
                    *(uint32_t*)(g_hf + (size_t)p*ND + nb) = *(uint32_t*)&hv;
                } else {
                    *(float2*)(g_y + (size_t)p*ND + nb) = make_float2(v0, v1);
                }
            }
        }
    }
}

// ---------------- coalesced residual (deep unroll for MLP) ----------------
__global__ void __launch_bounds__(256) resid_k(const float* __restrict__ x,
                                               float* __restrict__ out){
    __shared__ float sf[256];
    const int t = threadIdx.x;
    const int base = blockIdx.x * 256;            // first (b,d) row
    const int b = base >> 10;
    const int d = (base & 1023) + t;
    const int p0 = g_slot[2*b], p1 = g_slot[2*b+1];
    sf[t] = g_topw[2*b]   * g_y[(size_t)p0*DIM + d]
          + g_topw[2*b+1] * g_y[(size_t)p1*DIM + d];
    __syncthreads();
    const float4* xi = (const float4*)(x + (size_t)base*64);
    float4* o = (float4*)(out + (size_t)base*64);
#pragma unroll
    for (int blk=0; blk<2; blk++){
        float4 v[8]; float f[8]; int idx[8];
#pragma unroll
        for (int j=0;j<8;j++){
            idx[j] = t + (blk*8 + j)*256;
            v[j] = xi[idx[j]];
            f[j] = sf[idx[j] >> 4];
        }
#pragma unroll
        for (int j=0;j<8;j++){
            v[j].x += f[j]; v[j].y += f[j]; v[j].z += f[j]; v[j].w += f[j];
            o[idx[j]] = v[j];
        }
    }
}

// ---------------- launch ----------------
extern "C" void kernel_launch(void* const* d_in, const int* in_sizes, int n_in,
                              void* d_out, int out_size){
    const float* x     = (const float*)d_in[0];
    const float* gamma = (const float*)d_in[1];
    const float* beta  = (const float*)d_in[2];
    const float* wg    = (const float*)d_in[3];
    const float* bg    = (const float*)d_in[4];
    const float* w1    = (const float*)d_in[5];
    const float* b1    = (const float*)d_in[6];
    const float* w2    = (const float*)d_in[7];
    const float* b2    = (const float*)d_in[8];
    float* out = (float*)d_out;

    __half *w1f, *w2f;
    cudaGetSymbolAddress((void**)&w1f, g_w1f);
    cudaGetSymbolAddress((void**)&w2f, g_w2f);

    cudaFuncSetAttribute(gemm_k<DIM, HID, true,  true >, cudaFuncAttributeMaxDynamicSharedMemorySize, 196608);
    cudaFuncSetAttribute(gemm_k<HID, DIM, false, false>, cudaFuncAttributeMaxDynamicSharedMemorySize, 196608);

    pool_k<<<(BTOK*DIM*32)/256, 256>>>(x, w1, w2);     // 1: init + weight-convert + pool
    lngate_k<<<BTOK, 256>>>(gamma, beta, wg, bg);       // 2: LN + gate + (last block) scan/scatter
    gemm_k<DIM, HID, true,  true ><<<dim3(HID/256, MTILES), 256, 196608>>>(w1f, b1);   // 3
    gemm_k<HID, DIM, false, false><<<dim3(DIM/256, MTILES), 256, 196608>>>(w2f, b2);   // 4 <- ncu
    resid_k<<<(BTOK*DIM)/256, 256>>>(x, out);           // 5
}

// round 15
// speedup vs baseline: 1.1873x; 1.0397x over previous
#include <cuda_runtime.h>
#include <cuda_fp16.h>
#include <cstdint>
#include <math.h>

#define BTOK 4096
#define DIM 1024
#define HID 4096
#define NE 8
#define NSLOT (BTOK*2)
#define CAP 9216
#define MTILES (CAP/128)      // 72

// ---------------- scratch (device globals; no runtime allocation) ----------------
__device__ __align__(128) float  g_xn[BTOK*DIM];                 // pooled (fp32)
__device__ __align__(128) __half g_xf[BTOK*DIM];                 // x_norm fp16
__device__ __align__(128) __half g_hf[(size_t)CAP*HID];          // hidden fp16
__device__ __align__(128) float  g_y[(size_t)CAP*DIM];           // expert outputs
__device__ __align__(128) __half g_w1f[(size_t)NE*HID*DIM];
__device__ __align__(128) __half g_w2f[(size_t)NE*DIM*HID];
__device__ int   g_tok[CAP];
__device__ int   g_slot[NSLOT];
__device__ float g_topw[NSLOT];
__device__ int   g_topi[NSLOT];
__device__ int   g_cnt[NE];
__device__ int   g_off[NE+1];
__device__ int   g_tile_e[MTILES];

// ---------------- helpers ----------------
__device__ __forceinline__ void cp16(uint32_t dst, const void* src){
    asm volatile("cp.async.cg.shared.global [%0], [%1], 16;\n" :: "r"(dst), "l"(src));
}
__device__ __forceinline__ void mma_f16(float* c, const uint32_t* a, const uint32_t* b){
    asm volatile("mma.sync.aligned.m16n8k16.row.col.f32.f16.f16.f32 "
        "{%0,%1,%2,%3}, {%4,%5,%6,%7}, {%8,%9}, {%0,%1,%2,%3};"
        : "+f"(c[0]), "+f"(c[1]), "+f"(c[2]), "+f"(c[3])
        : "r"(a[0]), "r"(a[1]), "r"(a[2]), "r"(a[3]), "r"(b[0]), "r"(b[1]));
}
// word index in a [rows x 32-word] smem tile; 16B-unit swizzle u ^= (r&7)
__device__ __forceinline__ int swz32(int r, int w){
    return r*32 + (((((w>>2)) ^ (r & 7)) << 2) | (w & 3));
}
__device__ __forceinline__ uint2 h4(float4 v){
    __half2 lo = __floats2half2_rn(v.x, v.y);
    __half2 hi = __floats2half2_rn(v.z, v.w);
    uint2 r; r.x = *(uint32_t*)&lo; r.y = *(uint32_t*)&hi; return r;
}
// fast silu: MUFU-based exp + reciprocal-divide (err ~2^-21, invisible vs fp16 storage)
__device__ __forceinline__ float fsilu(float v){
    return __fdividef(v, 1.0f + __expf(-v));
}

// ---------------- fused init + weight-convert + pool ----------------
__global__ void pool_k(const float* __restrict__ x,
                       const float* __restrict__ w1, const float* __restrict__ w2){
    const int t = threadIdx.x;
    if (t < 32){
        size_t i = (size_t)blockIdx.x*16 + (t & 15);
        const float4* src = (t < 16) ? (const float4*)w1 : (const float4*)w2;
        __half* dst = (t < 16) ? g_w1f : g_w2f;
        *(uint2*)(dst + i*4) = h4(src[i]);
    }
    if (blockIdx.x == 0){
        if (t < NE) g_cnt[t] = 0;
        if (t < MTILES) g_tile_e[t] = -1;
        for (int i = t; i < CAP; i += 256) g_tok[i] = 0;
    }
    int g = blockIdx.x*blockDim.x + t;
    int row = g >> 5, lane = g & 31;
    float2 v = ((const float2*)(x + (size_t)row*64))[lane];
    float s = v.x + v.y;
#pragma unroll
    for (int o=16;o;o>>=1) s += __shfl_xor_sync(0xffffffffu, s, o);
    if (!lane) g_xn[row] = s * (1.0f/64.0f);
}

__global__ void __launch_bounds__(256) lngate_k(const float* __restrict__ gamma,
                                                const float* __restrict__ beta,
                                                const float* __restrict__ wg,
                                                const float* __restrict__ bg){
    const int b = blockIdx.x, t = threadIdx.x;
    __shared__ float srow[DIM];
    __shared__ float rs[8], rss[8], slog[8];
    float4 v = ((const float4*)(g_xn + (size_t)b*DIM))[t];
    float s  = (v.x+v.y)+(v.z+v.w);
    float ss = (v.x*v.x+v.y*v.y)+(v.z*v.z+v.w*v.w);
#pragma unroll
    for (int o=16;o;o>>=1){ s += __shfl_xor_sync(0xffffffffu, s, o); ss += __shfl_xor_sync(0xffffffffu, ss, o); }
    const int lane = t & 31, w = t >> 5;
    if (!lane){ rs[w]=s; rss[w]=ss; }
    __syncthreads();
    float tot=0.f, tot2=0.f;
#pragma unroll
    for (int i=0;i<8;i++){ tot += rs[i]; tot2 += rss[i]; }
    const float mean = tot * (1.0f/DIM);
    const float var  = tot2 * (1.0f/DIM) - mean*mean;
    const float rinv = rsqrtf(var + 1e-5f);
    float4 g4 = ((const float4*)gamma)[t];
    float4 be4 = ((const float4*)beta)[t];
    float4 xn;
    xn.x = (v.x-mean)*rinv*g4.x + be4.x;
    xn.y = (v.y-mean)*rinv*g4.y + be4.y;
    xn.z = (v.z-mean)*rinv*g4.z + be4.z;
    xn.w = (v.w-mean)*rinv*g4.w + be4.w;
    ((float4*)srow)[t] = xn;                 // full precision for gating
    *(uint2*)(g_xf + (size_t)b*DIM + 4*t) = h4(xn);
    __syncthreads();
    const float4* wrow = (const float4*)(wg + (size_t)w*DIM);
    const float4* sr = (const float4*)srow;
    float acc = 0.f;
#pragma unroll
    for (int i=0;i<8;i++){
        int idx = lane + i*32;
        float4 a = sr[idx], ww = wrow[idx];
        acc += a.x*ww.x + a.y*ww.y + a.z*ww.z + a.w*ww.w;
    }
#pragma unroll
    for (int o=16;o;o>>=1) acc += __shfl_xor_sync(0xffffffffu, acc, o);
    if (!lane) slog[w] = acc + bg[w];
    __syncthreads();
    if (!t){
        int e0 = 0;
#pragma unroll
        for (int i=1;i<8;i++) if (slog[i] > slog[e0]) e0 = i;
        int e1 = (e0==0) ? 1 : 0;
#pragma unroll
        for (int i=0;i<8;i++) if (i!=e0 && slog[i] > slog[e1]) e1 = i;
        float z = expf(slog[e1] - slog[e0]);      // v1 <= v0 (keep precise exp here)
        g_topi[b*2]=e0; g_topi[b*2+1]=e1;
        g_topw[b*2]=1.0f/(1.0f+z); g_topw[b*2+1]=z/(1.0f+z);
        atomicAdd(&g_cnt[e0],1); atomicAdd(&g_cnt[e1],1);
    }
}

// fused scan + scatter: single block, smem counters
__global__ void __launch_bounds__(256) scanscatter_k(){
    __shared__ int cur[NE];
    const int t = threadIdx.x;
    if (t == 0){
        int off = 0;
        for (int e=0;e<NE;e++){
            g_off[e] = off;
            int nt = (g_cnt[e] + 127) >> 7;
            int t0 = off >> 7;
            for (int i=0;i<nt;i++) g_tile_e[t0+i] = e;
            off += nt << 7;
        }
        g_off[NE] = off;
    }
    if (t < NE) cur[t] = 0;
    __syncthreads();
    for (int i=t; i<NSLOT; i+=256){
        int e = g_topi[i];
        int p = g_off[e] + atomicAdd(&cur[e], 1);
        g_tok[p] = i >> 1;
        g_slot[i] = p;
    }
}

// ---------------- fp16 mma GEMM: CTA tile 128x256, warp tile 64x64, K-chunk 64 ----------------
// 4-stage ring, 192KB, 1 CTA/SM; fast-silu epilogue (MUFU exp/rcp).
template<int KD, int ND, bool GATHER, bool SILU>
__global__ void __launch_bounds__(256) gemm_k(const __half* __restrict__ W,
                                              const float* __restrict__ bias){
    extern __shared__ __align__(16) char smem[];
    uint32_t* SW = (uint32_t*)smem;
    const int ntile = blockIdx.x, mtile = blockIdx.y;
    const int e = g_tile_e[mtile];
    if (e < 0) return;
    const int t = threadIdx.x;

    const int r0 = t >> 3, u = t & 7;                        // r0: 0..31, u: 16B unit
    const int adst0 = r0*32 + ((u ^ (r0 & 7)) << 2);         // words; +i*1024 per +32 rows

    const __half* aptr[4];
    if (GATHER){
#pragma unroll
        for (int i=0;i<4;i++)
            aptr[i] = g_xf + (size_t)g_tok[mtile*128 + r0 + i*32]*KD + u*8;
    } else {
        aptr[0] = g_hf + (size_t)(mtile*128 + r0)*KD + u*8;
    }
    const __half* bbase = W + ((size_t)e*ND + ntile*256 + r0)*KD + u*8;
    const float* bias_e = bias + (size_t)e*ND;
    uint32_t sAu = (uint32_t)__cvta_generic_to_shared(SW);

    const int NK = KD/64;
#pragma unroll
    for (int c=0;c<3;c++){
        const int ko = c*64;
        const uint32_t sb = sAu + (uint32_t)(c*12288 + adst0)*4u;
#pragma unroll
        for (int i=0;i<4;i++)
            cp16(sb + i*4096u, (GATHER ? aptr[i] : aptr[0] + (size_t)i*32*KD) + ko);
#pragma unroll
        for (int i=0;i<8;i++)
            cp16(sb + 16384u + i*4096u, bbase + (size_t)i*32*KD + ko);
        asm volatile("cp.async.commit_group;\n");
    }

    const int w = t>>5, lane = t&31;
    const int wm = w & 1, wn = w >> 1;        // 2 x 4 warp grid; warp tile 64x64
    const int lr = lane >> 2, lc = lane & 3;
    float acc[4][8][4];
#pragma unroll
    for (int a=0;a<4;a++)
#pragma unroll
        for (int bb=0;bb<8;bb++)
#pragma unroll
            for (int c=0;c<4;c++) acc[a][bb][c] = 0.f;

    for (int kc=0; kc<NK; kc++){
        const int buf = kc & 3;
        asm volatile("cp.async.wait_group 2;\n");
        __syncthreads();
        if (kc+3 < NK){
            const int ko = (kc+3)*64;
            const uint32_t sb = sAu + (uint32_t)(((kc+3)&3)*12288 + adst0)*4u;
#pragma unroll
            for (int i=0;i<4;i++)
                cp16(sb + i*4096u, (GATHER ? aptr[i] : aptr[0] + (size_t)i*32*KD) + ko);
#pragma unroll
            for (int i=0;i<8;i++)
                cp16(sb + 16384u + i*4096u, bbase + (size_t)i*32*KD + ko);
        }
        asm volatile("cp.async.commit_group;\n");

        const uint32_t* SA = SW + buf*12288;
        const uint32_t* SB = SA + 4096;
#pragma unroll
        for (int s=0;s<4;s++){
            const int w0 = s*8 + lc;
            uint32_t bfr[8][2];
#pragma unroll
            for (int ni=0;ni<8;ni++){
                const int n = wn*64 + ni*8 + lr;
                bfr[ni][0] = SB[swz32(n, w0)];
                bfr[ni][1] = SB[swz32(n, w0+4)];
            }
#pragma unroll
            for (int mi=0;mi<4;mi++){
                const int r = wm*64 + mi*16 + lr;
                uint32_t afr[4];
                afr[0] = SA[swz32(r,   w0)];
                afr[1] = SA[swz32(r+8, w0)];
                afr[2] = SA[swz32(r,   w0+4)];
                afr[3] = SA[swz32(r+8, w0+4)];
#pragma unroll
                for (int ni=0;ni<8;ni++)
                    mma_f16(acc[mi][ni], afr, bfr[ni]);
            }
        }
    }

#pragma unroll
    for (int mi=0;mi<4;mi++){
        const int rb = mtile*128 + wm*64 + mi*16 + lr;
#pragma unroll
        for (int ni=0;ni<8;ni++){
            const int nb = ntile*256 + wn*64 + ni*8 + lc*2;
            const float b0 = bias_e[nb], b1v = bias_e[nb+1];
#pragma unroll
            for (int h=0; h<2; h++){
                const int p = rb + h*8;
                float v0 = acc[mi][ni][h*2+0] + b0;
                float v1 = acc[mi][ni][h*2+1] + b1v;
                if (SILU){
                    v0 = fsilu(v0);
                    v1 = fsilu(v1);
                    __half2 hv = __floats2half2_rn(v0, v1);
                    *(uint32_t*)(g_hf + (size_t)p*ND + nb) = *(uint32_t*)&hv;
                } else {
                    *(float2*)(g_y + (size_t)p*ND + nb) = make_float2(v0, v1);
                }
            }
        }
    }
}

// ---------------- coalesced residual (deep unroll) ----------------
__global__ void __launch_bounds__(256) resid_k(const float* __restrict__ x,
                                               float* __restrict__ out){
    __shared__ float sf[256];
    const int t = threadIdx.x;
    const int base = blockIdx.x * 256;            // first (b,d) row
    const int b = base >> 10;
    const int d = (base & 1023) + t;
    const int p0 = g_slot[2*b], p1 = g_slot[2*b+1];
    sf[t] = g_topw[2*b]   * g_y[(size_t)p0*DIM + d]
          + g_topw[2*b+1] * g_y[(size_t)p1*DIM + d];
    __syncthreads();
    const float4* xi = (const float4*)(x + (size_t)base*64);
    float4* o = (float4*)(out + (size_t)base*64);
#pragma unroll
    for (int blk=0; blk<2; blk++){
        float4 v[8]; float f[8]; int idx[8];
#pragma unroll
        for (int j=0;j<8;j++){
            idx[j] = t + (blk*8 + j)*256;
            v[j] = xi[idx[j]];
            f[j] = sf[idx[j] >> 4];
        }
#pragma unroll
        for (int j=0;j<8;j++){
            v[j].x += f[j]; v[j].y += f[j]; v[j].z += f[j]; v[j].w += f[j];
            o[idx[j]] = v[j];
        }
    }
}

// ---------------- launch ----------------
extern "C" void kernel_launch(void* const* d_in, const int* in_sizes, int n_in,
                              void* d_out, int out_size){
    const float* x     = (const float*)d_in[0];
    const float* gamma = (const float*)d_in[1];
    const float* beta  = (const float*)d_in[2];
    const float* wg    = (const float*)d_in[3];
    const float* bg    = (const float*)d_in[4];
    const float* w1    = (const float*)d_in[5];
    const float* b1    = (const float*)d_in[6];
    const float* w2    = (const float*)d_in[7];
    const float* b2    = (const float*)d_in[8];
    float* out = (float*)d_out;

    __half *w1f, *w2f;
    cudaGetSymbolAddress((void**)&w1f, g_w1f);
    cudaGetSymbolAddress((void**)&w2f, g_w2f);

    cudaFuncSetAttribute(gemm_k<DIM, HID, true,  true >, cudaFuncAttributeMaxDynamicSharedMemorySize, 196608);
    cudaFuncSetAttribute(gemm_k<HID, DIM, false, false>, cudaFuncAttributeMaxDynamicSharedMemorySize, 196608);

    pool_k<<<(BTOK*DIM*32)/256, 256>>>(x, w1, w2);     // 1: init + weight-convert + pool
    lngate_k<<<BTOK, 256>>>(gamma, beta, wg, bg);       // 2
    scanscatter_k<<<1, 256>>>();                        // 3
    gemm_k<DIM, HID, true,  true ><<<dim3(HID/256, MTILES), 256, 196608>>>(w1f, b1);   // 4 <- ncu
    gemm_k<HID, DIM, false, false><<<dim3(DIM/256, MTILES), 256, 196608>>>(w2f, b2);   // 5
    resid_k<<<(BTOK*DIM)/256, 256>>>(x, out);           // 6
}